// round 5
// baseline (speedup 1.0000x reference)
#include <cuda_runtime.h>
#include <cuda_bf16.h>
#include <math.h>

#define N_NODES 100000
#define N_EDGES 3200000
#define SCAN_B  512
#define SCAN_NBLK ((N_NODES + SCAN_B - 1) / SCAN_B)   // 196

// ---------------- device scratch ----------------------------------------------
__device__ int   g_is64;
__device__ int   g_cnt[N_NODES];
__device__ int   g_rowptr[N_NODES + 1];
__device__ int   g_cursor[N_NODES];
__device__ int   g_srcs[N_EDGES];
__device__ int   g_blksum[SCAN_NBLK];
__device__ int   g_blkoff[SCAN_NBLK];
__device__ float g_dinv[N_NODES];
__device__ float g_bufA[N_NODES * 64];
__device__ float g_bufB[N_NODES * 64];

template <int TAG>
__device__ __forceinline__ float* buf_ptr() {
    return (TAG == 1) ? g_bufA : g_bufB;
}

__device__ __forceinline__ int edge_at(const void* ei, long long idx, int is64) {
    if (is64) return (int)((const long long*)ei)[idx];
    return ((const int*)ei)[idx];
}

// ---------------- dtype detection ----------------------------------------------
__global__ void k_detect(const void* ei) {
    __shared__ int any_nz;
    if (threadIdx.x == 0) any_nz = 0;
    __syncthreads();
    const int* w = (const int*)ei;
    for (int i = threadIdx.x; i < 4096; i += blockDim.x)
        if (w[2 * i + 1] != 0) any_nz = 1;
    __syncthreads();
    if (threadIdx.x == 0) g_is64 = any_nz ? 0 : 1;
}

// ---------------- CSR build -----------------------------------------------------
__global__ void k_init_cnt() {
    int i = blockIdx.x * blockDim.x + threadIdx.x;
    if (i < N_NODES) g_cnt[i] = 0;
}

__global__ void k_count(const void* __restrict__ ei) {
    int e = blockIdx.x * blockDim.x + threadIdx.x;
    if (e < N_EDGES) {
        int is64 = g_is64;
        int s = edge_at(ei, e, is64);
        int d = edge_at(ei, (long long)N_EDGES + e, is64);
        if ((unsigned)s < N_NODES && (unsigned)d < N_NODES)
            atomicAdd(&g_cnt[d], 1);
    }
}

__global__ __launch_bounds__(SCAN_B) void k_scan_local() {
    __shared__ int wsum[SCAN_B / 32];
    int tid  = threadIdx.x;
    int lane = tid & 31;
    int wid  = tid >> 5;
    int idx  = blockIdx.x * SCAN_B + tid;
    int v = (idx < N_NODES) ? g_cnt[idx] : 0;

    int incl = v;
#pragma unroll
    for (int off = 1; off < 32; off <<= 1) {
        int t = __shfl_up_sync(0xffffffffu, incl, off);
        if (lane >= off) incl += t;
    }
    if (lane == 31) wsum[wid] = incl;
    __syncthreads();
    if (wid == 0) {
        int ws = (lane < SCAN_B / 32) ? wsum[lane] : 0;
#pragma unroll
        for (int off = 1; off < SCAN_B / 32; off <<= 1) {
            int t = __shfl_up_sync(0xffffffffu, ws, off);
            if (lane >= off) ws += t;
        }
        if (lane < SCAN_B / 32) wsum[lane] = ws;
    }
    __syncthreads();
    int base = (wid > 0) ? wsum[wid - 1] : 0;
    if (idx < N_NODES) g_rowptr[idx] = base + incl - v;
    if (tid == SCAN_B - 1) g_blksum[blockIdx.x] = base + incl;
}

__global__ __launch_bounds__(256) void k_scan_blk() {
    __shared__ int sh[256];
    int tid = threadIdx.x;
    int v = (tid < SCAN_NBLK) ? g_blksum[tid] : 0;
    sh[tid] = v;
    __syncthreads();
#pragma unroll
    for (int off = 1; off < 256; off <<= 1) {
        int t = (tid >= off) ? sh[tid - off] : 0;
        __syncthreads();
        sh[tid] += t;
        __syncthreads();
    }
    if (tid < SCAN_NBLK) g_blkoff[tid] = sh[tid] - v;
}

__global__ __launch_bounds__(256) void k_scan_add() {
    int i = blockIdx.x * blockDim.x + threadIdx.x;
    if (i < N_NODES) {
        int rp = g_rowptr[i] + g_blkoff[i / SCAN_B];
        g_rowptr[i] = rp;
        g_cursor[i] = rp;
        g_dinv[i]   = rsqrtf((float)g_cnt[i] + 1.0f);  // +1 self loop
    }
    if (i == 0) g_rowptr[N_NODES] =
        g_blkoff[SCAN_NBLK - 1] + g_blksum[SCAN_NBLK - 1];
}

__global__ void k_fill(const void* __restrict__ ei) {
    int e = blockIdx.x * blockDim.x + threadIdx.x;
    if (e < N_EDGES) {
        int is64 = g_is64;
        int s = edge_at(ei, e, is64);
        int d = edge_at(ei, (long long)N_EDGES + e, is64);
        if ((unsigned)s < N_NODES && (unsigned)d < N_NODES) {
            int p = atomicAdd(&g_cursor[d], 1);
            g_srcs[p] = s;
        }
    }
}

// ---------------- layer-1 prep: A[n,34] = x[n,34] * dinv[n] ---------------------
__global__ __launch_bounds__(256) void k_prep34(const float* __restrict__ x) {
    int idx = blockIdx.x * blockDim.x + threadIdx.x;
    if (idx >= N_NODES * 34) return;
    int node = idx / 34;
    g_bufA[idx] = x[idx] * g_dinv[node];
}

// ---------------- layer-1 aggregate in 34-dim input space ------------------------
// B[i,34] = dinv[i] * (A[i,:] + sum_{src->i} A[src,:])      (rows = 17 float2)
__global__ __launch_bounds__(256) void k_agg34() {
    const float2* tmp2 = (const float2*)g_bufA;
    float2* out2 = (float2*)g_bufB;
    int warp = (blockIdx.x * blockDim.x + threadIdx.x) >> 5;
    int lane = threadIdx.x & 31;
    if (warp >= N_NODES) return;
    const int node = warp;
    const bool act = lane < 17;

    float ax0 = 0.f, ay0 = 0.f, ax1 = 0.f, ay1 = 0.f;
    if (act) {
        float2 s = tmp2[(size_t)node * 17 + lane];
        ax0 = s.x; ay0 = s.y;
    }

    int start = g_rowptr[node];
    int end   = g_rowptr[node + 1];
    int e0 = start;
    for (; e0 + 32 <= end; e0 += 32) {          // full blocks: static unroll
        int s = g_srcs[e0 + lane];
#pragma unroll
        for (int j = 0; j < 32; j += 2) {
            int s0 = __shfl_sync(0xffffffffu, s, j);
            int s1 = __shfl_sync(0xffffffffu, s, j + 1);
            if (act) {
                float2 r0 = tmp2[(size_t)s0 * 17 + lane];
                float2 r1 = tmp2[(size_t)s1 * 17 + lane];
                ax0 += r0.x; ay0 += r0.y;
                ax1 += r1.x; ay1 += r1.y;
            }
        }
    }
    if (e0 < end) {                              // remainder
        int m = end - e0;
        int s = (e0 + lane < end) ? g_srcs[e0 + lane] : 0;
        for (int j = 0; j < m; j++) {
            int sj = __shfl_sync(0xffffffffu, s, j);
            if (act) {
                float2 r = tmp2[(size_t)sj * 17 + lane];
                ax0 += r.x; ay0 += r.y;
            }
        }
    }
    if (act) {
        float d = g_dinv[node];
        float2 o;
        o.x = d * (ax0 + ax1);
        o.y = d * (ay0 + ay1);
        out2[(size_t)node * 17 + lane] = o;
    }
}

// ---------------- GEMM variants ---------------------------------------------------
// DST[n,FOUT] = tanh(SRC[n,FIN] @ W + b)
template <int FIN, int FOUT, int SRC_TAG, int DST_TAG>
__global__ __launch_bounds__(256) void k_gemm_bias_tanh(
    const float* __restrict__ W, const float* __restrict__ b)
{
    __shared__ float sW[FIN * FOUT];
    for (int i = threadIdx.x; i < FIN * FOUT; i += blockDim.x) sW[i] = W[i];
    __syncthreads();
    const float* h = buf_ptr<SRC_TAG>();
    float* out = buf_ptr<DST_TAG>();
    int idx = blockIdx.x * blockDim.x + threadIdx.x;
    int node = idx / FOUT;
    int f    = idx % FOUT;
    if (node >= N_NODES) return;
    const float* hr = h + (size_t)node * FIN;
    float acc = b[f];
#pragma unroll
    for (int k = 0; k < FIN; k++) acc += hr[k] * sW[k * FOUT + f];
    out[(size_t)node * FOUT + f] = tanhf(acc);
}

// DST[n,FOUT] = (SRC[n,FIN] @ W) * dinv[n]
template <int FIN, int FOUT, int SRC_TAG, int DST_TAG>
__global__ __launch_bounds__(256) void k_gemm_scale(const float* __restrict__ W)
{
    __shared__ float sW[FIN * FOUT];
    for (int i = threadIdx.x; i < FIN * FOUT; i += blockDim.x) sW[i] = W[i];
    __syncthreads();
    const float* h = buf_ptr<SRC_TAG>();
    float* out = buf_ptr<DST_TAG>();
    int idx = blockIdx.x * blockDim.x + threadIdx.x;
    int node = idx / FOUT;
    int f    = idx % FOUT;
    if (node >= N_NODES) return;
    const float* hr = h + (size_t)node * FIN;
    float acc = 0.f;
#pragma unroll
    for (int k = 0; k < FIN; k++) acc += hr[k] * sW[k * FOUT + f];
    out[(size_t)node * FOUT + f] = acc * g_dinv[node];
}

// ---------------- aggregation FOUT<=32, SPLIT subgroups, 4-way unroll -------------
template <int FOUT, int SRC_TAG, int DST_TAG>
__global__ __launch_bounds__(256) void k_aggregate_small(const float* __restrict__ b)
{
    constexpr int SPLIT = 32 / FOUT;
    const float* tmp = buf_ptr<SRC_TAG>();
    float* out = buf_ptr<DST_TAG>();
    int warp = (blockIdx.x * blockDim.x + threadIdx.x) >> 5;
    int lane = threadIdx.x & 31;
    if (warp >= N_NODES) return;
    const int node = warp;
    int sub = lane / FOUT;
    int f   = lane % FOUT;

    float a0 = (sub == 0) ? tmp[(size_t)node * FOUT + f] : 0.f;  // self loop
    float a1 = 0.f, a2 = 0.f, a3 = 0.f;

    int start = g_rowptr[node];
    int end   = g_rowptr[node + 1];
    int e = start + sub;
    for (; e + 3 * SPLIT < end; e += 4 * SPLIT) {
        int s0 = g_srcs[e];
        int s1 = g_srcs[e + SPLIT];
        int s2 = g_srcs[e + 2 * SPLIT];
        int s3 = g_srcs[e + 3 * SPLIT];
        a0 += tmp[(size_t)s0 * FOUT + f];
        a1 += tmp[(size_t)s1 * FOUT + f];
        a2 += tmp[(size_t)s2 * FOUT + f];
        a3 += tmp[(size_t)s3 * FOUT + f];
    }
    for (; e < end; e += SPLIT) a0 += tmp[(size_t)g_srcs[e] * FOUT + f];
    a0 += a1 + a2 + a3;

#pragma unroll
    for (int off = FOUT; off < 32; off <<= 1)
        a0 += __shfl_xor_sync(0xffffffffu, a0, off);

    if (sub == 0) {
        float v = g_dinv[node] * a0 + b[f];
        out[(size_t)node * FOUT + f] = tanhf(v);
    }
}

// ---------------- final layer: aggregate FOUT=8 + classifier, writes d_out --------
// d_out layout: [N*2 logits][N*8 hidden]
template <int SRC_TAG>
__global__ __launch_bounds__(256) void k_agg8_classify(
    const float* __restrict__ b, const float* __restrict__ Wc,
    const float* __restrict__ bc, float* __restrict__ dout)
{
    constexpr int FOUT = 8, SPLIT = 4;
    const float* tmp = buf_ptr<SRC_TAG>();
    int warp = (blockIdx.x * blockDim.x + threadIdx.x) >> 5;
    int lane = threadIdx.x & 31;
    if (warp >= N_NODES) return;
    const int node = warp;
    int sub = lane / FOUT;
    int f   = lane % FOUT;

    float a0 = (sub == 0) ? tmp[(size_t)node * FOUT + f] : 0.f;
    float a1 = 0.f, a2 = 0.f, a3 = 0.f;

    int start = g_rowptr[node];
    int end   = g_rowptr[node + 1];
    int e = start + sub;
    for (; e + 3 * SPLIT < end; e += 4 * SPLIT) {
        int s0 = g_srcs[e];
        int s1 = g_srcs[e + SPLIT];
        int s2 = g_srcs[e + 2 * SPLIT];
        int s3 = g_srcs[e + 3 * SPLIT];
        a0 += tmp[(size_t)s0 * FOUT + f];
        a1 += tmp[(size_t)s1 * FOUT + f];
        a2 += tmp[(size_t)s2 * FOUT + f];
        a3 += tmp[(size_t)s3 * FOUT + f];
    }
    for (; e < end; e += SPLIT) a0 += tmp[(size_t)g_srcs[e] * FOUT + f];
    a0 += a1 + a2 + a3;

#pragma unroll
    for (int off = FOUT; off < 32; off <<= 1)
        a0 += __shfl_xor_sync(0xffffffffu, a0, off);

    // lanes 0..7 (sub==0) now hold the pre-activation for feature f
    float h = tanhf(g_dinv[node] * a0 + b[f]);

    // classifier: logit_c = bc[c] + sum_f h_f * Wc[f*2+c]
    float p0 = h * Wc[f * 2 + 0];
    float p1 = h * Wc[f * 2 + 1];
#pragma unroll
    for (int off = 1; off < 8; off <<= 1) {
        p0 += __shfl_xor_sync(0xffffffffu, p0, off);
        p1 += __shfl_xor_sync(0xffffffffu, p1, off);
    }

    if (sub == 0) {
        float* dh = dout + (size_t)2 * N_NODES;
        dh[(size_t)node * 8 + f] = h;
        if (f == 0) {
            dout[(size_t)node * 2 + 0] = p0 + bc[0];
            dout[(size_t)node * 2 + 1] = p1 + bc[1];
        }
    }
}

// ---------------- launcher --------------------------------------------------------
extern "C" void kernel_launch(void* const* d_in, const int* in_sizes, int n_in,
                              void* d_out, int out_size)
{
    const float* x  = (const float*)d_in[0];
    const void*  ei = d_in[1];
    const float* W1 = (const float*)d_in[2];
    const float* b1 = (const float*)d_in[3];
    const float* W2 = (const float*)d_in[4];
    const float* b2 = (const float*)d_in[5];
    const float* W3 = (const float*)d_in[6];
    const float* b3 = (const float*)d_in[7];
    const float* W4 = (const float*)d_in[8];
    const float* b4 = (const float*)d_in[9];
    const float* Wc = (const float*)d_in[10];
    const float* bc = (const float*)d_in[11];
    float* out = (float*)d_out;

    const int T = 256;
    const int eb = (N_EDGES + T - 1) / T;
    const int nb = (N_NODES + T - 1) / T;
    const int wb = (N_NODES * 32 + T - 1) / T;  // one warp per node

    // dtype detection + CSR build (by dst)
    k_detect<<<1, 256>>>(ei);
    k_init_cnt<<<nb, T>>>();
    k_count<<<eb, T>>>(ei);
    k_scan_local<<<SCAN_NBLK, SCAN_B>>>();
    k_scan_blk<<<1, 256>>>();
    k_scan_add<<<nb, T>>>();
    k_fill<<<eb, T>>>(ei);

    // layer 1: aggregate in input space (34), then GEMM 34->64 + bias + tanh
    k_prep34<<<(N_NODES * 34 + T - 1) / T, T>>>(x);             // x -> A
    k_agg34<<<wb, T>>>();                                       // A -> B
    k_gemm_bias_tanh<34, 64, 2, 1><<<(N_NODES * 64 + T - 1) / T, T>>>(W1, b1); // B -> A (h1)

    // layer 2: GEMM 64->32 (*dinv), aggregate(32) + bias + tanh
    k_gemm_scale<64, 32, 1, 2><<<(N_NODES * 32 + T - 1) / T, T>>>(W2);  // A -> B
    k_aggregate_small<32, 2, 1><<<wb, T>>>(b2);                          // B -> A (h2)

    // layer 3
    k_gemm_scale<32, 16, 1, 2><<<(N_NODES * 16 + T - 1) / T, T>>>(W3);  // A -> B
    k_aggregate_small<16, 2, 1><<<wb, T>>>(b3);                          // B -> A (h3)

    // layer 4 + classifier fused
    k_gemm_scale<16, 8, 1, 2><<<(N_NODES * 8 + T - 1) / T, T>>>(W4);    // A -> B
    k_agg8_classify<2><<<wb, T>>>(b4, Wc, bc, out);                      // B -> d_out
}

// round 6
// speedup vs baseline: 1.0631x; 1.0631x over previous
#include <cuda_runtime.h>
#include <cuda_fp16.h>
#include <math.h>

#define N_NODES 100000
#define N_EDGES 3200000
#define SCAN_B  512
#define SCAN_NBLK ((N_NODES + SCAN_B - 1) / SCAN_B)   // 196

// ---------------- device scratch ----------------------------------------------
__device__ int    g_is64;
__device__ int    g_cnt[N_NODES];
__device__ int    g_rowptr[N_NODES + 1];
__device__ int    g_cursor[N_NODES];
__device__ int    g_srcs[N_EDGES];
__device__ int    g_blksum[SCAN_NBLK];
__device__ int    g_blkoff[SCAN_NBLK];
__device__ float  g_dinv[N_NODES];
__device__ float  g_bufA[N_NODES * 64];
__device__ float  g_bufB[N_NODES * 64];
__device__ __half g_bufH[N_NODES * 64];   // fp16 gather buffer (layers 1,2)

template <int TAG>
__device__ __forceinline__ float* buf_ptr() {
    return (TAG == 1) ? g_bufA : g_bufB;
}

// ---------------- dtype detection ----------------------------------------------
__global__ void k_detect(const void* ei) {
    __shared__ int any_nz;
    if (threadIdx.x == 0) any_nz = 0;
    __syncthreads();
    const int* w = (const int*)ei;
    for (int i = threadIdx.x; i < 4096; i += blockDim.x)
        if (w[2 * i + 1] != 0) any_nz = 1;
    __syncthreads();
    if (threadIdx.x == 0) g_is64 = any_nz ? 0 : 1;
}

// ---------------- CSR build -----------------------------------------------------
__global__ void k_init_cnt() {
    int i = blockIdx.x * blockDim.x + threadIdx.x;
    if (i < N_NODES) g_cnt[i] = 0;
}

__global__ void k_count(const void* __restrict__ ei) {
    int e = blockIdx.x * blockDim.x + threadIdx.x;
    if (e < N_EDGES) {
        int d = g_is64 ? (int)((const long long*)ei)[(long long)N_EDGES + e]
                       : ((const int*)ei)[N_EDGES + e];
        if ((unsigned)d < N_NODES) atomicAdd(&g_cnt[d], 1);
    }
}

__global__ __launch_bounds__(SCAN_B) void k_scan_local() {
    __shared__ int wsum[SCAN_B / 32];
    int tid  = threadIdx.x;
    int lane = tid & 31;
    int wid  = tid >> 5;
    int idx  = blockIdx.x * SCAN_B + tid;
    int v = (idx < N_NODES) ? g_cnt[idx] : 0;

    int incl = v;
#pragma unroll
    for (int off = 1; off < 32; off <<= 1) {
        int t = __shfl_up_sync(0xffffffffu, incl, off);
        if (lane >= off) incl += t;
    }
    if (lane == 31) wsum[wid] = incl;
    __syncthreads();
    if (wid == 0) {
        int ws = (lane < SCAN_B / 32) ? wsum[lane] : 0;
#pragma unroll
        for (int off = 1; off < SCAN_B / 32; off <<= 1) {
            int t = __shfl_up_sync(0xffffffffu, ws, off);
            if (lane >= off) ws += t;
        }
        if (lane < SCAN_B / 32) wsum[lane] = ws;
    }
    __syncthreads();
    int base = (wid > 0) ? wsum[wid - 1] : 0;
    if (idx < N_NODES) g_rowptr[idx] = base + incl - v;
    if (tid == SCAN_B - 1) g_blksum[blockIdx.x] = base + incl;
}

__global__ __launch_bounds__(256) void k_scan_blk() {
    __shared__ int sh[256];
    int tid = threadIdx.x;
    int v = (tid < SCAN_NBLK) ? g_blksum[tid] : 0;
    sh[tid] = v;
    __syncthreads();
#pragma unroll
    for (int off = 1; off < 256; off <<= 1) {
        int t = (tid >= off) ? sh[tid - off] : 0;
        __syncthreads();
        sh[tid] += t;
        __syncthreads();
    }
    if (tid < SCAN_NBLK) g_blkoff[tid] = sh[tid] - v;
}

__global__ __launch_bounds__(256) void k_scan_add() {
    int i = blockIdx.x * blockDim.x + threadIdx.x;
    if (i < N_NODES) {
        int rp = g_rowptr[i] + g_blkoff[i / SCAN_B];
        g_rowptr[i] = rp;
        g_cursor[i] = rp;
        g_dinv[i]   = rsqrtf((float)g_cnt[i] + 1.0f);  // +1 self loop
    }
    if (i == 0) g_rowptr[N_NODES] =
        g_blkoff[SCAN_NBLK - 1] + g_blksum[SCAN_NBLK - 1];
}

__global__ void k_fill(const void* __restrict__ ei) {
    int e = blockIdx.x * blockDim.x + threadIdx.x;
    if (e < N_EDGES) {
        int is64 = g_is64;
        int s, d;
        if (is64) {
            s = (int)((const long long*)ei)[e];
            d = (int)((const long long*)ei)[(long long)N_EDGES + e];
        } else {
            s = ((const int*)ei)[e];
            d = ((const int*)ei)[N_EDGES + e];
        }
        if ((unsigned)d < N_NODES) {
            int p = atomicAdd(&g_cursor[d], 1);
            g_srcs[p] = s;
        }
    }
}

// ---------------- GEMM -> fp16 buffer: H[n,FOUT] = half((SRC @ W) * dinv[n]) ----
// SRC_TAG 0 => ext pointer, else float buffer
template <int FIN, int FOUT, int SRC_TAG>
__global__ __launch_bounds__(256) void k_gemm_scale_h(
    const float* __restrict__ ext, const float* __restrict__ W)
{
    __shared__ float sW[FIN * FOUT];
    for (int i = threadIdx.x; i < FIN * FOUT; i += blockDim.x) sW[i] = W[i];
    __syncthreads();
    const float* h = (SRC_TAG == 0) ? ext : buf_ptr<SRC_TAG>();
    int idx = blockIdx.x * blockDim.x + threadIdx.x;
    int node = idx / FOUT;
    int f    = idx % FOUT;
    if (node >= N_NODES) return;
    const float* hr = h + (size_t)node * FIN;
    float acc = 0.f;
#pragma unroll
    for (int k = 0; k < FIN; k++) acc += hr[k] * sW[k * FOUT + f];
    g_bufH[(size_t)node * FOUT + f] = __float2half(acc * g_dinv[node]);
}

// GEMM float->float: DST[n,FOUT] = (SRC @ W) * dinv[n]
template <int FIN, int FOUT, int SRC_TAG, int DST_TAG>
__global__ __launch_bounds__(256) void k_gemm_scale(const float* __restrict__ W)
{
    __shared__ float sW[FIN * FOUT];
    for (int i = threadIdx.x; i < FIN * FOUT; i += blockDim.x) sW[i] = W[i];
    __syncthreads();
    const float* h = buf_ptr<SRC_TAG>();
    float* out = buf_ptr<DST_TAG>();
    int idx = blockIdx.x * blockDim.x + threadIdx.x;
    int node = idx / FOUT;
    int f    = idx % FOUT;
    if (node >= N_NODES) return;
    const float* hr = h + (size_t)node * FIN;
    float acc = 0.f;
#pragma unroll
    for (int k = 0; k < FIN; k++) acc += hr[k] * sW[k * FOUT + f];
    out[(size_t)node * FOUT + f] = acc * g_dinv[node];
}

// ---------------- aggregate 64-dim fp16 -> float (layer 1) ----------------------
// rows: 32 half2 per node = 128B = exactly one L2 line per edge gather
template <int DST_TAG>
__global__ __launch_bounds__(256) void k_agg64h(const float* __restrict__ b)
{
    const __half2* t = (const __half2*)g_bufH;
    float2* out2 = (float2*)buf_ptr<DST_TAG>();
    int warp = (blockIdx.x * blockDim.x + threadIdx.x) >> 5;
    int lane = threadIdx.x & 31;
    if (warp >= N_NODES) return;
    const int node = warp;

    float2 self = __half22float2(t[(size_t)node * 32 + lane]);
    float ax0 = self.x, ay0 = self.y, ax1 = 0.f, ay1 = 0.f;

    int start = g_rowptr[node];
    int end   = g_rowptr[node + 1];
    int e0 = start;
    for (; e0 + 32 <= end; e0 += 32) {
        int s = g_srcs[e0 + lane];
#pragma unroll
        for (int j = 0; j < 32; j += 2) {
            int s0 = __shfl_sync(0xffffffffu, s, j);
            int s1 = __shfl_sync(0xffffffffu, s, j + 1);
            float2 r0 = __half22float2(t[(size_t)s0 * 32 + lane]);
            float2 r1 = __half22float2(t[(size_t)s1 * 32 + lane]);
            ax0 += r0.x; ay0 += r0.y;
            ax1 += r1.x; ay1 += r1.y;
        }
    }
    if (e0 < end) {
        int m = end - e0;
        int s = (e0 + lane < end) ? g_srcs[e0 + lane] : 0;
        for (int j = 0; j < m; j++) {
            int sj = __shfl_sync(0xffffffffu, s, j);
            float2 r = __half22float2(t[(size_t)sj * 32 + lane]);
            ax0 += r.x; ay0 += r.y;
        }
    }
    float d = g_dinv[node];
    float2 bv = ((const float2*)b)[lane];
    float2 o;
    o.x = tanhf(d * (ax0 + ax1) + bv.x);
    o.y = tanhf(d * (ay0 + ay1) + bv.y);
    out2[(size_t)node * 32 + lane] = o;
}

// ---------------- aggregate 32-dim fp16 -> float (layer 2) ----------------------
// rows: 16 half2 = 64B; 2 edge-subgroups per warp (16 lanes each)
template <int DST_TAG>
__global__ __launch_bounds__(256) void k_agg32h(const float* __restrict__ b)
{
    const __half2* t = (const __half2*)g_bufH;
    float2* out2 = (float2*)buf_ptr<DST_TAG>();
    int warp = (blockIdx.x * blockDim.x + threadIdx.x) >> 5;
    int lane = threadIdx.x & 31;
    if (warp >= N_NODES) return;
    const int node = warp;
    int sub = lane >> 4;          // 0 or 1
    int c   = lane & 15;          // half2 column

    float ax = 0.f, ay = 0.f, bx = 0.f, by = 0.f;
    if (sub == 0) {
        float2 s = __half22float2(t[(size_t)node * 16 + c]);
        ax = s.x; ay = s.y;
    }

    int start = g_rowptr[node];
    int end   = g_rowptr[node + 1];
    int e = start + sub;
    for (; e + 6 < end; e += 8) {
        int s0 = g_srcs[e];
        int s1 = g_srcs[e + 2];
        int s2 = g_srcs[e + 4];
        int s3 = g_srcs[e + 6];
        float2 r0 = __half22float2(t[(size_t)s0 * 16 + c]);
        float2 r1 = __half22float2(t[(size_t)s1 * 16 + c]);
        float2 r2 = __half22float2(t[(size_t)s2 * 16 + c]);
        float2 r3 = __half22float2(t[(size_t)s3 * 16 + c]);
        ax += r0.x; ay += r0.y;
        bx += r1.x; by += r1.y;
        ax += r2.x; ay += r2.y;
        bx += r3.x; by += r3.y;
    }
    for (; e < end; e += 2) {
        float2 r = __half22float2(t[(size_t)g_srcs[e] * 16 + c]);
        ax += r.x; ay += r.y;
    }
    ax += bx; ay += by;
    ax += __shfl_xor_sync(0xffffffffu, ax, 16);
    ay += __shfl_xor_sync(0xffffffffu, ay, 16);

    if (sub == 0) {
        float d = g_dinv[node];
        float2 bv = ((const float2*)b)[c];
        float2 o;
        o.x = tanhf(d * ax + bv.x);
        o.y = tanhf(d * ay + bv.y);
        out2[(size_t)node * 16 + c] = o;
    }
}

// ---------------- aggregate FOUT<=32 fp32 (layers 3) ----------------------------
template <int FOUT, int SRC_TAG, int DST_TAG>
__global__ __launch_bounds__(256) void k_aggregate_small(const float* __restrict__ b)
{
    constexpr int SPLIT = 32 / FOUT;
    const float* tmp = buf_ptr<SRC_TAG>();
    float* out = buf_ptr<DST_TAG>();
    int warp = (blockIdx.x * blockDim.x + threadIdx.x) >> 5;
    int lane = threadIdx.x & 31;
    if (warp >= N_NODES) return;
    const int node = warp;
    int sub = lane / FOUT;
    int f   = lane % FOUT;

    float a0 = (sub == 0) ? tmp[(size_t)node * FOUT + f] : 0.f;
    float a1 = 0.f, a2 = 0.f, a3 = 0.f;

    int start = g_rowptr[node];
    int end   = g_rowptr[node + 1];
    int e = start + sub;
    for (; e + 3 * SPLIT < end; e += 4 * SPLIT) {
        int s0 = g_srcs[e];
        int s1 = g_srcs[e + SPLIT];
        int s2 = g_srcs[e + 2 * SPLIT];
        int s3 = g_srcs[e + 3 * SPLIT];
        a0 += tmp[(size_t)s0 * FOUT + f];
        a1 += tmp[(size_t)s1 * FOUT + f];
        a2 += tmp[(size_t)s2 * FOUT + f];
        a3 += tmp[(size_t)s3 * FOUT + f];
    }
    for (; e < end; e += SPLIT) a0 += tmp[(size_t)g_srcs[e] * FOUT + f];
    a0 += a1 + a2 + a3;

#pragma unroll
    for (int off = FOUT; off < 32; off <<= 1)
        a0 += __shfl_xor_sync(0xffffffffu, a0, off);

    if (sub == 0) {
        float v = g_dinv[node] * a0 + b[f];
        out[(size_t)node * FOUT + f] = tanhf(v);
    }
}

// ---------------- final: aggregate FOUT=8 + classifier -> d_out -----------------
template <int SRC_TAG>
__global__ __launch_bounds__(256) void k_agg8_classify(
    const float* __restrict__ b, const float* __restrict__ Wc,
    const float* __restrict__ bc, float* __restrict__ dout)
{
    constexpr int FOUT = 8, SPLIT = 4;
    const float* tmp = buf_ptr<SRC_TAG>();
    int warp = (blockIdx.x * blockDim.x + threadIdx.x) >> 5;
    int lane = threadIdx.x & 31;
    if (warp >= N_NODES) return;
    const int node = warp;
    int sub = lane / FOUT;
    int f   = lane % FOUT;

    float a0 = (sub == 0) ? tmp[(size_t)node * FOUT + f] : 0.f;
    float a1 = 0.f, a2 = 0.f, a3 = 0.f;

    int start = g_rowptr[node];
    int end   = g_rowptr[node + 1];
    int e = start + sub;
    for (; e + 3 * SPLIT < end; e += 4 * SPLIT) {
        int s0 = g_srcs[e];
        int s1 = g_srcs[e + SPLIT];
        int s2 = g_srcs[e + 2 * SPLIT];
        int s3 = g_srcs[e + 3 * SPLIT];
        a0 += tmp[(size_t)s0 * FOUT + f];
        a1 += tmp[(size_t)s1 * FOUT + f];
        a2 += tmp[(size_t)s2 * FOUT + f];
        a3 += tmp[(size_t)s3 * FOUT + f];
    }
    for (; e < end; e += SPLIT) a0 += tmp[(size_t)g_srcs[e] * FOUT + f];
    a0 += a1 + a2 + a3;

#pragma unroll
    for (int off = FOUT; off < 32; off <<= 1)
        a0 += __shfl_xor_sync(0xffffffffu, a0, off);

    float h = tanhf(g_dinv[node] * a0 + b[f]);

    float p0 = h * Wc[f * 2 + 0];
    float p1 = h * Wc[f * 2 + 1];
#pragma unroll
    for (int off = 1; off < 8; off <<= 1) {
        p0 += __shfl_xor_sync(0xffffffffu, p0, off);
        p1 += __shfl_xor_sync(0xffffffffu, p1, off);
    }

    if (sub == 0) {
        float* dh = dout + (size_t)2 * N_NODES;
        dh[(size_t)node * 8 + f] = h;
        if (f == 0) {
            dout[(size_t)node * 2 + 0] = p0 + bc[0];
            dout[(size_t)node * 2 + 1] = p1 + bc[1];
        }
    }
}

// ---------------- launcher --------------------------------------------------------
extern "C" void kernel_launch(void* const* d_in, const int* in_sizes, int n_in,
                              void* d_out, int out_size)
{
    const float* x  = (const float*)d_in[0];
    const void*  ei = d_in[1];
    const float* W1 = (const float*)d_in[2];
    const float* b1 = (const float*)d_in[3];
    const float* W2 = (const float*)d_in[4];
    const float* b2 = (const float*)d_in[5];
    const float* W3 = (const float*)d_in[6];
    const float* b3 = (const float*)d_in[7];
    const float* W4 = (const float*)d_in[8];
    const float* b4 = (const float*)d_in[9];
    const float* Wc = (const float*)d_in[10];
    const float* bc = (const float*)d_in[11];
    float* out = (float*)d_out;

    const int T = 256;
    const int eb = (N_EDGES + T - 1) / T;
    const int nb = (N_NODES + T - 1) / T;
    const int wb = (N_NODES * 32 + T - 1) / T;  // one warp per node

    // dtype detection + CSR build (by dst)
    k_detect<<<1, 256>>>(ei);
    k_init_cnt<<<nb, T>>>();
    k_count<<<eb, T>>>(ei);
    k_scan_local<<<SCAN_NBLK, SCAN_B>>>();
    k_scan_blk<<<1, 256>>>();
    k_scan_add<<<nb, T>>>();
    k_fill<<<eb, T>>>(ei);

    // layer 1: GEMM 34->64 (*dinv) to fp16, aggregate 64d fp16 (+bias+tanh)
    k_gemm_scale_h<34, 64, 0><<<(N_NODES * 64 + T - 1) / T, T>>>(x, W1); // x -> H
    k_agg64h<1><<<wb, T>>>(b1);                                          // H -> A (h1)

    // layer 2: GEMM 64->32 (*dinv) to fp16, aggregate 32d fp16
    k_gemm_scale_h<64, 32, 1><<<(N_NODES * 32 + T - 1) / T, T>>>(nullptr, W2); // A -> H
    k_agg32h<2><<<wb, T>>>(b2);                                                 // H -> B (h2)

    // layer 3: fp32
    k_gemm_scale<32, 16, 2, 1><<<(N_NODES * 16 + T - 1) / T, T>>>(W3);  // B -> A
    k_aggregate_small<16, 1, 2><<<wb, T>>>(b3);                          // A -> B (h3)

    // layer 4 + classifier fused (fp32)
    k_gemm_scale<16, 8, 2, 1><<<(N_NODES * 8 + T - 1) / T, T>>>(W4);    // B -> A
    k_agg8_classify<1><<<wb, T>>>(b4, Wc, bc, out);                      // A -> d_out
}

// round 7
// speedup vs baseline: 1.1610x; 1.0920x over previous
#include <cuda_runtime.h>
#include <cuda_fp16.h>
#include <math.h>

#define N_NODES 100000
#define N_EDGES 3200000
#define SCAN_B  512
#define SCAN_NBLK ((N_NODES + SCAN_B - 1) / SCAN_B)   // 196
#define FULLM 0xffffffffu

// ---------------- device scratch ----------------------------------------------
__device__ int    g_is64;
__device__ int    g_cnt[N_NODES];
__device__ int    g_rowptr[N_NODES + 1];
__device__ int    g_cursor[N_NODES];
__device__ int    g_srcs[N_EDGES];
__device__ int    g_blksum[SCAN_NBLK];
__device__ int    g_blkoff[SCAN_NBLK];
__device__ float  g_dinv[N_NODES];
__device__ __half g_H1[N_NODES * 64];   // layer-1 gather buf (128B rows)
__device__ __half g_H2[N_NODES * 32];   // layer-2 gather buf (64B rows)
__device__ __half g_H3[N_NODES * 16];   // layer-3 gather buf (32B rows)
__device__ __half g_H4[N_NODES * 8];    // layer-4 gather buf (16B rows)

// ---------------- init: zero cnt + dtype detect ---------------------------------
__global__ __launch_bounds__(256) void k_init(const void* ei) {
    int i = blockIdx.x * blockDim.x + threadIdx.x;
    if (i < N_NODES) g_cnt[i] = 0;
    if (blockIdx.x == 0) {
        __shared__ int any_nz;
        if (threadIdx.x == 0) any_nz = 0;
        __syncthreads();
        const int* w = (const int*)ei;
        for (int k = threadIdx.x; k < 4096; k += blockDim.x)
            if (w[2 * k + 1] != 0) any_nz = 1;
        __syncthreads();
        if (threadIdx.x == 0) g_is64 = any_nz ? 0 : 1;
    }
}

// ---------------- CSR build -----------------------------------------------------
__global__ void k_count(const void* __restrict__ ei) {
    int e = blockIdx.x * blockDim.x + threadIdx.x;
    if (e < N_EDGES) {
        int d = g_is64 ? (int)((const long long*)ei)[(long long)N_EDGES + e]
                       : ((const int*)ei)[N_EDGES + e];
        if ((unsigned)d < N_NODES) atomicAdd(&g_cnt[d], 1);
    }
}

__global__ __launch_bounds__(SCAN_B) void k_scan_local() {
    __shared__ int wsum[SCAN_B / 32];
    int tid  = threadIdx.x;
    int lane = tid & 31;
    int wid  = tid >> 5;
    int idx  = blockIdx.x * SCAN_B + tid;
    int v = (idx < N_NODES) ? g_cnt[idx] : 0;

    int incl = v;
#pragma unroll
    for (int off = 1; off < 32; off <<= 1) {
        int t = __shfl_up_sync(FULLM, incl, off);
        if (lane >= off) incl += t;
    }
    if (lane == 31) wsum[wid] = incl;
    __syncthreads();
    if (wid == 0) {
        int ws = (lane < SCAN_B / 32) ? wsum[lane] : 0;
#pragma unroll
        for (int off = 1; off < SCAN_B / 32; off <<= 1) {
            int t = __shfl_up_sync(FULLM, ws, off);
            if (lane >= off) ws += t;
        }
        if (lane < SCAN_B / 32) wsum[lane] = ws;
    }
    __syncthreads();
    int base = (wid > 0) ? wsum[wid - 1] : 0;
    if (idx < N_NODES) g_rowptr[idx] = base + incl - v;
    if (tid == SCAN_B - 1) g_blksum[blockIdx.x] = base + incl;
}

__global__ __launch_bounds__(256) void k_scan_blk() {
    __shared__ int sh[256];
    int tid = threadIdx.x;
    int v = (tid < SCAN_NBLK) ? g_blksum[tid] : 0;
    sh[tid] = v;
    __syncthreads();
#pragma unroll
    for (int off = 1; off < 256; off <<= 1) {
        int t = (tid >= off) ? sh[tid - off] : 0;
        __syncthreads();
        sh[tid] += t;
        __syncthreads();
    }
    if (tid < SCAN_NBLK) g_blkoff[tid] = sh[tid] - v;
}

__global__ __launch_bounds__(256) void k_scan_add() {
    int i = blockIdx.x * blockDim.x + threadIdx.x;
    if (i < N_NODES) {
        int rp = g_rowptr[i] + g_blkoff[i / SCAN_B];
        g_rowptr[i] = rp;
        g_cursor[i] = rp;
        g_dinv[i]   = rsqrtf((float)g_cnt[i] + 1.0f);  // +1 self loop
    }
    if (i == 0) g_rowptr[N_NODES] =
        g_blkoff[SCAN_NBLK - 1] + g_blksum[SCAN_NBLK - 1];
}

__global__ void k_fill(const void* __restrict__ ei) {
    int e = blockIdx.x * blockDim.x + threadIdx.x;
    if (e < N_EDGES) {
        int is64 = g_is64;
        int s, d;
        if (is64) {
            s = (int)((const long long*)ei)[e];
            d = (int)((const long long*)ei)[(long long)N_EDGES + e];
        } else {
            s = ((const int*)ei)[e];
            d = ((const int*)ei)[N_EDGES + e];
        }
        if ((unsigned)d < N_NODES) {
            int p = atomicAdd(&g_cursor[d], 1);
            g_srcs[p] = s;
        }
    }
}

// ---------------- layer-1 GEMM: H1[n,64] = half((x[n,34] @ W1) * dinv[n]) -------
__global__ __launch_bounds__(256) void k_gemm1(
    const float* __restrict__ x, const float* __restrict__ W)
{
    __shared__ float sW[34 * 64];
    for (int i = threadIdx.x; i < 34 * 64; i += blockDim.x) sW[i] = W[i];
    __syncthreads();
    int idx = blockIdx.x * blockDim.x + threadIdx.x;
    int node = idx >> 6;
    int f    = idx & 63;
    if (node >= N_NODES) return;
    const float* hr = x + (size_t)node * 34;
    float acc = 0.f;
#pragma unroll
    for (int k = 0; k < 34; k++) acc += hr[k] * sW[k * 64 + f];
    g_H1[(size_t)node * 64 + f] = __float2half(acc * g_dinv[node]);
}

// ---------------- F1: aggregate 64d + tanh + GEMM 64->32 -> H2 ------------------
__global__ __launch_bounds__(256) void k_f1(
    const float* __restrict__ b1, const float* __restrict__ W2)
{
    __shared__ float sW[64 * 32];   // 8KB
    for (int i = threadIdx.x; i < 64 * 32; i += blockDim.x) sW[i] = W2[i];
    __syncthreads();

    int warp = (blockIdx.x * blockDim.x + threadIdx.x) >> 5;
    int lane = threadIdx.x & 31;
    if (warp >= N_NODES) return;
    const int node = warp;
    const __half2* t = (const __half2*)g_H1;

    float2 self = __half22float2(t[(size_t)node * 32 + lane]);
    float ax0 = self.x, ay0 = self.y, ax1 = 0.f, ay1 = 0.f;

    int start = g_rowptr[node];
    int end   = g_rowptr[node + 1];
    int e0 = start;
    for (; e0 + 32 <= end; e0 += 32) {
        int s = g_srcs[e0 + lane];
#pragma unroll
        for (int j = 0; j < 32; j += 2) {
            int s0 = __shfl_sync(FULLM, s, j);
            int s1 = __shfl_sync(FULLM, s, j + 1);
            float2 r0 = __half22float2(t[(size_t)s0 * 32 + lane]);
            float2 r1 = __half22float2(t[(size_t)s1 * 32 + lane]);
            ax0 += r0.x; ay0 += r0.y;
            ax1 += r1.x; ay1 += r1.y;
        }
    }
    if (e0 < end) {
        int m = end - e0;
        int s = (e0 + lane < end) ? g_srcs[e0 + lane] : 0;
        for (int j = 0; j < m; j++) {
            int sj = __shfl_sync(FULLM, s, j);
            float2 r = __half22float2(t[(size_t)sj * 32 + lane]);
            ax0 += r.x; ay0 += r.y;
        }
    }
    float d = g_dinv[node];
    float2 bv = ((const float2*)b1)[lane];
    float hx = tanhf(d * (ax0 + ax1) + bv.x);   // h1[2*lane]
    float hy = tanhf(d * (ay0 + ay1) + bv.y);   // h1[2*lane+1]

    // GEMM 64->32: lane f computes sum_k h1[k]*W2[k,f]
    float acc = 0.f;
#pragma unroll
    for (int k = 0; k < 32; k++) {
        float x0 = __shfl_sync(FULLM, hx, k);
        float x1 = __shfl_sync(FULLM, hy, k);
        acc += x0 * sW[(2 * k) * 32 + lane] + x1 * sW[(2 * k + 1) * 32 + lane];
    }
    g_H2[(size_t)node * 32 + lane] = __float2half(acc * d);
}

// ---------------- F2: aggregate 32d + tanh + GEMM 32->16 -> H3 ------------------
__global__ __launch_bounds__(256) void k_f2(
    const float* __restrict__ b2, const float* __restrict__ W3)
{
    __shared__ float sW[32 * 16];
    for (int i = threadIdx.x; i < 32 * 16; i += blockDim.x) sW[i] = W3[i];
    __syncthreads();

    int warp = (blockIdx.x * blockDim.x + threadIdx.x) >> 5;
    int lane = threadIdx.x & 31;
    if (warp >= N_NODES) return;
    const int node = warp;
    const __half2* t = (const __half2*)g_H2;
    int sub = lane >> 4;
    int c   = lane & 15;

    float ax = 0.f, ay = 0.f, bx = 0.f, by = 0.f;
    if (sub == 0) {
        float2 s = __half22float2(t[(size_t)node * 16 + c]);
        ax = s.x; ay = s.y;
    }
    int start = g_rowptr[node];
    int end   = g_rowptr[node + 1];
    int e = start + sub;
    for (; e + 6 < end; e += 8) {
        int s0 = g_srcs[e];
        int s1 = g_srcs[e + 2];
        int s2 = g_srcs[e + 4];
        int s3 = g_srcs[e + 6];
        float2 r0 = __half22float2(t[(size_t)s0 * 16 + c]);
        float2 r1 = __half22float2(t[(size_t)s1 * 16 + c]);
        float2 r2 = __half22float2(t[(size_t)s2 * 16 + c]);
        float2 r3 = __half22float2(t[(size_t)s3 * 16 + c]);
        ax += r0.x; ay += r0.y;
        bx += r1.x; by += r1.y;
        ax += r2.x; ay += r2.y;
        bx += r3.x; by += r3.y;
    }
    for (; e < end; e += 2) {
        float2 r = __half22float2(t[(size_t)g_srcs[e] * 16 + c]);
        ax += r.x; ay += r.y;
    }
    ax += bx; ay += by;
    ax += __shfl_xor_sync(FULLM, ax, 16);
    ay += __shfl_xor_sync(FULLM, ay, 16);

    float d = g_dinv[node];
    float2 bv = ((const float2*)b2)[c];
    float hx = tanhf(d * ax + bv.x);    // h2[2c]   (all lanes hold pair for c)
    float hy = tanhf(d * ay + bv.y);    // h2[2c+1]

    // GEMM 32->16: lanes 0..15 compute f = lane
    float acc = 0.f;
#pragma unroll
    for (int k = 0; k < 16; k++) {
        float x0 = __shfl_sync(FULLM, hx, k);
        float x1 = __shfl_sync(FULLM, hy, k);
        acc += x0 * sW[(2 * k) * 16 + c] + x1 * sW[(2 * k + 1) * 16 + c];
    }
    if (sub == 0)
        g_H3[(size_t)node * 16 + c] = __float2half(acc * d);
}

// ---------------- F3: aggregate 16d + tanh + GEMM 16->8 -> H4 -------------------
__global__ __launch_bounds__(256) void k_f3(
    const float* __restrict__ b3, const float* __restrict__ W4)
{
    __shared__ float sW[16 * 8];
    for (int i = threadIdx.x; i < 16 * 8; i += blockDim.x) sW[i] = W4[i];
    __syncthreads();

    int warp = (blockIdx.x * blockDim.x + threadIdx.x) >> 5;
    int lane = threadIdx.x & 31;
    if (warp >= N_NODES) return;
    const int node = warp;
    const __half2* t = (const __half2*)g_H3;
    int sub = lane >> 3;          // 4 subgroups
    int c   = lane & 7;

    float ax = 0.f, ay = 0.f, bx = 0.f, by = 0.f;
    if (sub == 0) {
        float2 s = __half22float2(t[(size_t)node * 8 + c]);
        ax = s.x; ay = s.y;
    }
    int start = g_rowptr[node];
    int end   = g_rowptr[node + 1];
    int e = start + sub;
    for (; e + 12 < end; e += 16) {
        int s0 = g_srcs[e];
        int s1 = g_srcs[e + 4];
        int s2 = g_srcs[e + 8];
        int s3 = g_srcs[e + 12];
        float2 r0 = __half22float2(t[(size_t)s0 * 8 + c]);
        float2 r1 = __half22float2(t[(size_t)s1 * 8 + c]);
        float2 r2 = __half22float2(t[(size_t)s2 * 8 + c]);
        float2 r3 = __half22float2(t[(size_t)s3 * 8 + c]);
        ax += r0.x; ay += r0.y;
        bx += r1.x; by += r1.y;
        ax += r2.x; ay += r2.y;
        bx += r3.x; by += r3.y;
    }
    for (; e < end; e += 4) {
        float2 r = __half22float2(t[(size_t)g_srcs[e] * 8 + c]);
        ax += r.x; ay += r.y;
    }
    ax += bx; ay += by;
    ax += __shfl_xor_sync(FULLM, ax, 8);
    ay += __shfl_xor_sync(FULLM, ay, 8);
    ax += __shfl_xor_sync(FULLM, ax, 16);
    ay += __shfl_xor_sync(FULLM, ay, 16);

    float d = g_dinv[node];
    float2 bv = ((const float2*)b3)[c];
    float hx = tanhf(d * ax + bv.x);    // h3[2c]
    float hy = tanhf(d * ay + bv.y);

    // GEMM 16->8: lanes 0..7 compute f = c
    float acc = 0.f;
#pragma unroll
    for (int k = 0; k < 8; k++) {
        float x0 = __shfl_sync(FULLM, hx, k);
        float x1 = __shfl_sync(FULLM, hy, k);
        acc += x0 * sW[(2 * k) * 8 + c] + x1 * sW[(2 * k + 1) * 8 + c];
    }
    if (sub == 0)
        g_H4[(size_t)node * 8 + c] = __float2half(acc * d);
}

// ---------------- F4: aggregate 8d + tanh + classifier -> d_out -----------------
// d_out: [N*2 logits][N*8 hidden]
__global__ __launch_bounds__(256) void k_f4(
    const float* __restrict__ b4, const float* __restrict__ Wc,
    const float* __restrict__ bc, float* __restrict__ dout)
{
    int warp = (blockIdx.x * blockDim.x + threadIdx.x) >> 5;
    int lane = threadIdx.x & 31;
    if (warp >= N_NODES) return;
    const int node = warp;
    const __half2* t = (const __half2*)g_H4;
    int sub = lane >> 2;          // 8 subgroups
    int c   = lane & 3;

    float ax = 0.f, ay = 0.f, bx = 0.f, by = 0.f;
    if (sub == 0) {
        float2 s = __half22float2(t[(size_t)node * 4 + c]);
        ax = s.x; ay = s.y;
    }
    int start = g_rowptr[node];
    int end   = g_rowptr[node + 1];
    int e = start + sub;
    for (; e + 24 < end; e += 32) {
        int s0 = g_srcs[e];
        int s1 = g_srcs[e + 8];
        int s2 = g_srcs[e + 16];
        int s3 = g_srcs[e + 24];
        float2 r0 = __half22float2(t[(size_t)s0 * 4 + c]);
        float2 r1 = __half22float2(t[(size_t)s1 * 4 + c]);
        float2 r2 = __half22float2(t[(size_t)s2 * 4 + c]);
        float2 r3 = __half22float2(t[(size_t)s3 * 4 + c]);
        ax += r0.x; ay += r0.y;
        bx += r1.x; by += r1.y;
        ax += r2.x; ay += r2.y;
        bx += r3.x; by += r3.y;
    }
    for (; e < end; e += 8) {
        float2 r = __half22float2(t[(size_t)g_srcs[e] * 4 + c]);
        ax += r.x; ay += r.y;
    }
    ax += bx; ay += by;
    ax += __shfl_xor_sync(FULLM, ax, 4);
    ay += __shfl_xor_sync(FULLM, ay, 4);
    ax += __shfl_xor_sync(FULLM, ax, 8);
    ay += __shfl_xor_sync(FULLM, ay, 8);
    ax += __shfl_xor_sync(FULLM, ax, 16);
    ay += __shfl_xor_sync(FULLM, ay, 16);

    float d = g_dinv[node];
    float hx = tanhf(d * ax + b4[2 * c]);      // h4[2c]
    float hy = tanhf(d * ay + b4[2 * c + 1]);  // h4[2c+1]

    // classifier: logits over 8 features (pairs on lanes c=0..3)
    float p0 = hx * Wc[(2 * c) * 2 + 0] + hy * Wc[(2 * c + 1) * 2 + 0];
    float p1 = hx * Wc[(2 * c) * 2 + 1] + hy * Wc[(2 * c + 1) * 2 + 1];
    p0 += __shfl_xor_sync(FULLM, p0, 1);
    p1 += __shfl_xor_sync(FULLM, p1, 1);
    p0 += __shfl_xor_sync(FULLM, p0, 2);
    p1 += __shfl_xor_sync(FULLM, p1, 2);

    if (sub == 0) {
        float2* dh = (float2*)(dout + (size_t)2 * N_NODES);
        dh[(size_t)node * 4 + c] = make_float2(hx, hy);
        if (c == 0) {
            dout[(size_t)node * 2 + 0] = p0 + bc[0];
            dout[(size_t)node * 2 + 1] = p1 + bc[1];
        }
    }
}

// ---------------- launcher --------------------------------------------------------
extern "C" void kernel_launch(void* const* d_in, const int* in_sizes, int n_in,
                              void* d_out, int out_size)
{
    const float* x  = (const float*)d_in[0];
    const void*  ei = d_in[1];
    const float* W1 = (const float*)d_in[2];
    const float* b1 = (const float*)d_in[3];
    const float* W2 = (const float*)d_in[4];
    const float* b2 = (const float*)d_in[5];
    const float* W3 = (const float*)d_in[6];
    const float* b3 = (const float*)d_in[7];
    const float* W4 = (const float*)d_in[8];
    const float* b4 = (const float*)d_in[9];
    const float* Wc = (const float*)d_in[10];
    const float* bc = (const float*)d_in[11];
    float* out = (float*)d_out;

    const int T = 256;
    const int eb = (N_EDGES + T - 1) / T;
    const int nb = (N_NODES + T - 1) / T;
    const int wb = (N_NODES * 32 + T - 1) / T;  // one warp per node

    // CSR build (by dst) + dinv
    k_init<<<nb, T>>>(ei);
    k_count<<<eb, T>>>(ei);
    k_scan_local<<<SCAN_NBLK, SCAN_B>>>();
    k_scan_blk<<<1, 256>>>();
    k_scan_add<<<nb, T>>>();
    k_fill<<<eb, T>>>(ei);

    // pipeline: gemm1 -> F1 -> F2 -> F3 -> F4
    k_gemm1<<<(N_NODES * 64 + T - 1) / T, T>>>(x, W1);
    k_f1<<<wb, T>>>(b1, W2);
    k_f2<<<wb, T>>>(b2, W3);
    k_f3<<<wb, T>>>(b3, W4);
    k_f4<<<wb, T>>>(b4, Wc, bc, out);
}

// round 8
// speedup vs baseline: 1.1765x; 1.0134x over previous
#include <cuda_runtime.h>
#include <cuda_fp16.h>
#include <math.h>

#define N_NODES 100000
#define N_EDGES 3200000
#define SCAN_B  512
#define SCAN_NBLK ((N_NODES + SCAN_B - 1) / SCAN_B)   // 196
#define FULLM 0xffffffffu
#define TB 256
#define EB ((N_EDGES + TB - 1) / TB)                  // fill blocks
#define GB ((N_NODES * 64 + TB - 1) / TB)             // gemm1 blocks

// ---------------- device scratch ----------------------------------------------
__device__ int    g_is64;
__device__ int    g_cnt[N_NODES];
__device__ int    g_rowptr[N_NODES + 1];
__device__ int    g_cursor[N_NODES];
__device__ int    g_srcs[N_EDGES];
__device__ int    g_blksum[SCAN_NBLK];
__device__ int    g_blkoff[SCAN_NBLK];
__device__ float  g_dinv[N_NODES];
__device__ __half g_H1[N_NODES * 64];   // layer-1 gather buf (128B rows)
__device__ __half g_H2[N_NODES * 32];   // layer-2 gather buf (64B rows)
__device__ __half g_H3[N_NODES * 16];   // layer-3 gather buf (32B rows)
__device__ float  g_H4[N_NODES * 8];    // layer-4 gather buf (32B rows, fp32)

// ---------------- init: zero cnt + dtype detect ---------------------------------
__global__ __launch_bounds__(TB) void k_init(const void* ei) {
    int i = blockIdx.x * blockDim.x + threadIdx.x;
    if (i < N_NODES) g_cnt[i] = 0;
    if (blockIdx.x == 0) {
        __shared__ int any_nz;
        if (threadIdx.x == 0) any_nz = 0;
        __syncthreads();
        const int* w = (const int*)ei;
        for (int k = threadIdx.x; k < 4096; k += blockDim.x)
            if (w[2 * k + 1] != 0) any_nz = 1;
        __syncthreads();
        if (threadIdx.x == 0) g_is64 = any_nz ? 0 : 1;
    }
}

// ---------------- CSR build -----------------------------------------------------
__global__ void k_count(const void* __restrict__ ei) {
    int e = blockIdx.x * blockDim.x + threadIdx.x;
    if (e < N_EDGES) {
        int d = g_is64 ? (int)((const long long*)ei)[(long long)N_EDGES + e]
                       : ((const int*)ei)[N_EDGES + e];
        if ((unsigned)d < N_NODES) atomicAdd(&g_cnt[d], 1);
    }
}

__global__ __launch_bounds__(SCAN_B) void k_scan_local() {
    __shared__ int wsum[SCAN_B / 32];
    int tid  = threadIdx.x;
    int lane = tid & 31;
    int wid  = tid >> 5;
    int idx  = blockIdx.x * SCAN_B + tid;
    int v = (idx < N_NODES) ? g_cnt[idx] : 0;

    int incl = v;
#pragma unroll
    for (int off = 1; off < 32; off <<= 1) {
        int t = __shfl_up_sync(FULLM, incl, off);
        if (lane >= off) incl += t;
    }
    if (lane == 31) wsum[wid] = incl;
    __syncthreads();
    if (wid == 0) {
        int ws = (lane < SCAN_B / 32) ? wsum[lane] : 0;
#pragma unroll
        for (int off = 1; off < SCAN_B / 32; off <<= 1) {
            int t = __shfl_up_sync(FULLM, ws, off);
            if (lane >= off) ws += t;
        }
        if (lane < SCAN_B / 32) wsum[lane] = ws;
    }
    __syncthreads();
    int base = (wid > 0) ? wsum[wid - 1] : 0;
    if (idx < N_NODES) g_rowptr[idx] = base + incl - v;
    if (tid == SCAN_B - 1) g_blksum[blockIdx.x] = base + incl;
}

__global__ __launch_bounds__(256) void k_scan_blk() {
    __shared__ int sh[256];
    int tid = threadIdx.x;
    int v = (tid < SCAN_NBLK) ? g_blksum[tid] : 0;
    sh[tid] = v;
    __syncthreads();
#pragma unroll
    for (int off = 1; off < 256; off <<= 1) {
        int t = (tid >= off) ? sh[tid - off] : 0;
        __syncthreads();
        sh[tid] += t;
        __syncthreads();
    }
    if (tid < SCAN_NBLK) g_blkoff[tid] = sh[tid] - v;
}

__global__ __launch_bounds__(256) void k_scan_add() {
    int i = blockIdx.x * blockDim.x + threadIdx.x;
    if (i < N_NODES) {
        int rp = g_rowptr[i] + g_blkoff[i / SCAN_B];
        g_rowptr[i] = rp;
        g_cursor[i] = rp;
        g_dinv[i]   = rsqrtf((float)g_cnt[i] + 1.0f);  // +1 self loop
    }
    if (i == 0) g_rowptr[N_NODES] =
        g_blkoff[SCAN_NBLK - 1] + g_blksum[SCAN_NBLK - 1];
}

// ---------------- fused: CSR fill + layer-1 GEMM (co-scheduled) ------------------
// blocks [0, EB): fill g_srcs; blocks [EB, EB+GB): H1 = half((x @ W1)*dinv)
__global__ __launch_bounds__(TB) void k_fill_gemm1(
    const void* __restrict__ ei, const float* __restrict__ x,
    const float* __restrict__ W)
{
    __shared__ float sW[34 * 64];
    if (blockIdx.x < EB) {
        int e = blockIdx.x * TB + threadIdx.x;
        if (e < N_EDGES) {
            int is64 = g_is64;
            int s, d;
            if (is64) {
                s = (int)((const long long*)ei)[e];
                d = (int)((const long long*)ei)[(long long)N_EDGES + e];
            } else {
                s = ((const int*)ei)[e];
                d = ((const int*)ei)[N_EDGES + e];
            }
            if ((unsigned)d < N_NODES) {
                int p = atomicAdd(&g_cursor[d], 1);
                g_srcs[p] = s;
            }
        }
    } else {
        for (int i = threadIdx.x; i < 34 * 64; i += blockDim.x) sW[i] = W[i];
        __syncthreads();
        int idx = (blockIdx.x - EB) * TB + threadIdx.x;
        int node = idx >> 6;
        int f    = idx & 63;
        if (node >= N_NODES) return;
        const float* hr = x + (size_t)node * 34;
        float acc = 0.f;
#pragma unroll
        for (int k = 0; k < 34; k++) acc += hr[k] * sW[k * 64 + f];
        g_H1[(size_t)node * 64 + f] = __float2half(acc * g_dinv[node]);
    }
}

// ---------------- F1: aggregate 64d + tanh + GEMM 64->32 -> H2 ------------------
__global__ __launch_bounds__(256) void k_f1(
    const float* __restrict__ b1, const float* __restrict__ W2)
{
    __shared__ float sW[64 * 32];   // 8KB
    for (int i = threadIdx.x; i < 64 * 32; i += blockDim.x) sW[i] = W2[i];
    __syncthreads();

    int warp = (blockIdx.x * blockDim.x + threadIdx.x) >> 5;
    int lane = threadIdx.x & 31;
    if (warp >= N_NODES) return;
    const int node = warp;
    const __half2* t = (const __half2*)g_H1;

    float2 self = __half22float2(t[(size_t)node * 32 + lane]);
    float ax0 = self.x, ay0 = self.y, ax1 = 0.f, ay1 = 0.f;

    int start = g_rowptr[node];
    int end   = g_rowptr[node + 1];
    int e0 = start;
    for (; e0 + 32 <= end; e0 += 32) {
        int s = g_srcs[e0 + lane];
#pragma unroll
        for (int j = 0; j < 32; j += 2) {
            int s0 = __shfl_sync(FULLM, s, j);
            int s1 = __shfl_sync(FULLM, s, j + 1);
            float2 r0 = __half22float2(t[(size_t)s0 * 32 + lane]);
            float2 r1 = __half22float2(t[(size_t)s1 * 32 + lane]);
            ax0 += r0.x; ay0 += r0.y;
            ax1 += r1.x; ay1 += r1.y;
        }
    }
    if (e0 < end) {
        int m = end - e0;
        int s = (e0 + lane < end) ? g_srcs[e0 + lane] : 0;
        for (int j = 0; j < m; j++) {
            int sj = __shfl_sync(FULLM, s, j);
            float2 r = __half22float2(t[(size_t)sj * 32 + lane]);
            ax0 += r.x; ay0 += r.y;
        }
    }
    float d = g_dinv[node];
    float2 bv = ((const float2*)b1)[lane];
    float hx = tanhf(d * (ax0 + ax1) + bv.x);   // h1[2*lane]
    float hy = tanhf(d * (ay0 + ay1) + bv.y);   // h1[2*lane+1]

    // GEMM 64->32: lane f computes sum_k h1[k]*W2[k,f]
    float acc = 0.f;
#pragma unroll
    for (int k = 0; k < 32; k++) {
        float x0 = __shfl_sync(FULLM, hx, k);
        float x1 = __shfl_sync(FULLM, hy, k);
        acc += x0 * sW[(2 * k) * 32 + lane] + x1 * sW[(2 * k + 1) * 32 + lane];
    }
    g_H2[(size_t)node * 32 + lane] = __float2half(acc * d);
}

// ---------------- F2: aggregate 32d + tanh + GEMM 32->16 -> H3 ------------------
__global__ __launch_bounds__(256) void k_f2(
    const float* __restrict__ b2, const float* __restrict__ W3)
{
    __shared__ float sW[32 * 16];
    for (int i = threadIdx.x; i < 32 * 16; i += blockDim.x) sW[i] = W3[i];
    __syncthreads();

    int warp = (blockIdx.x * blockDim.x + threadIdx.x) >> 5;
    int lane = threadIdx.x & 31;
    if (warp >= N_NODES) return;
    const int node = warp;
    const __half2* t = (const __half2*)g_H2;
    int sub = lane >> 4;
    int c   = lane & 15;

    float ax = 0.f, ay = 0.f, bx = 0.f, by = 0.f;
    if (sub == 0) {
        float2 s = __half22float2(t[(size_t)node * 16 + c]);
        ax = s.x; ay = s.y;
    }
    int start = g_rowptr[node];
    int end   = g_rowptr[node + 1];
    int e = start + sub;
    for (; e + 14 < end; e += 16) {      // 8-way unroll (stride 2)
        int s0 = g_srcs[e];
        int s1 = g_srcs[e + 2];
        int s2 = g_srcs[e + 4];
        int s3 = g_srcs[e + 6];
        int s4 = g_srcs[e + 8];
        int s5 = g_srcs[e + 10];
        int s6 = g_srcs[e + 12];
        int s7 = g_srcs[e + 14];
        float2 r0 = __half22float2(t[(size_t)s0 * 16 + c]);
        float2 r1 = __half22float2(t[(size_t)s1 * 16 + c]);
        float2 r2 = __half22float2(t[(size_t)s2 * 16 + c]);
        float2 r3 = __half22float2(t[(size_t)s3 * 16 + c]);
        float2 r4 = __half22float2(t[(size_t)s4 * 16 + c]);
        float2 r5 = __half22float2(t[(size_t)s5 * 16 + c]);
        float2 r6 = __half22float2(t[(size_t)s6 * 16 + c]);
        float2 r7 = __half22float2(t[(size_t)s7 * 16 + c]);
        ax += r0.x; ay += r0.y;  bx += r1.x; by += r1.y;
        ax += r2.x; ay += r2.y;  bx += r3.x; by += r3.y;
        ax += r4.x; ay += r4.y;  bx += r5.x; by += r5.y;
        ax += r6.x; ay += r6.y;  bx += r7.x; by += r7.y;
    }
    for (; e < end; e += 2) {
        float2 r = __half22float2(t[(size_t)g_srcs[e] * 16 + c]);
        ax += r.x; ay += r.y;
    }
    ax += bx; ay += by;
    ax += __shfl_xor_sync(FULLM, ax, 16);
    ay += __shfl_xor_sync(FULLM, ay, 16);

    float d = g_dinv[node];
    float2 bv = ((const float2*)b2)[c];
    float hx = tanhf(d * ax + bv.x);    // h2[2c]
    float hy = tanhf(d * ay + bv.y);    // h2[2c+1]

    // GEMM 32->16: lanes 0..15 compute f = c
    float acc = 0.f;
#pragma unroll
    for (int k = 0; k < 16; k++) {
        float x0 = __shfl_sync(FULLM, hx, k);
        float x1 = __shfl_sync(FULLM, hy, k);
        acc += x0 * sW[(2 * k) * 16 + c] + x1 * sW[(2 * k + 1) * 16 + c];
    }
    if (sub == 0)
        g_H3[(size_t)node * 16 + c] = __float2half(acc * d);
}

// ---------------- F3: aggregate 16d + tanh + GEMM 16->8 -> H4 (fp32) ------------
__global__ __launch_bounds__(256) void k_f3(
    const float* __restrict__ b3, const float* __restrict__ W4)
{
    __shared__ float sW[16 * 8];
    for (int i = threadIdx.x; i < 16 * 8; i += blockDim.x) sW[i] = W4[i];
    __syncthreads();

    int warp = (blockIdx.x * blockDim.x + threadIdx.x) >> 5;
    int lane = threadIdx.x & 31;
    if (warp >= N_NODES) return;
    const int node = warp;
    const __half2* t = (const __half2*)g_H3;
    int sub = lane >> 3;          // 4 subgroups
    int c   = lane & 7;

    float ax = 0.f, ay = 0.f, bx = 0.f, by = 0.f;
    if (sub == 0) {
        float2 s = __half22float2(t[(size_t)node * 8 + c]);
        ax = s.x; ay = s.y;
    }
    int start = g_rowptr[node];
    int end   = g_rowptr[node + 1];
    int e = start + sub;
    for (; e + 12 < end; e += 16) {
        int s0 = g_srcs[e];
        int s1 = g_srcs[e + 4];
        int s2 = g_srcs[e + 8];
        int s3 = g_srcs[e + 12];
        float2 r0 = __half22float2(t[(size_t)s0 * 8 + c]);
        float2 r1 = __half22float2(t[(size_t)s1 * 8 + c]);
        float2 r2 = __half22float2(t[(size_t)s2 * 8 + c]);
        float2 r3 = __half22float2(t[(size_t)s3 * 8 + c]);
        ax += r0.x; ay += r0.y;
        bx += r1.x; by += r1.y;
        ax += r2.x; ay += r2.y;
        bx += r3.x; by += r3.y;
    }
    for (; e < end; e += 4) {
        float2 r = __half22float2(t[(size_t)g_srcs[e] * 8 + c]);
        ax += r.x; ay += r.y;
    }
    ax += bx; ay += by;
    ax += __shfl_xor_sync(FULLM, ax, 8);
    ay += __shfl_xor_sync(FULLM, ay, 8);
    ax += __shfl_xor_sync(FULLM, ax, 16);
    ay += __shfl_xor_sync(FULLM, ay, 16);

    float d = g_dinv[node];
    float2 bv = ((const float2*)b3)[c];
    float hx = tanhf(d * ax + bv.x);    // h3[2c]
    float hy = tanhf(d * ay + bv.y);

    // GEMM 16->8: lanes 0..7 compute f = c
    float acc = 0.f;
#pragma unroll
    for (int k = 0; k < 8; k++) {
        float x0 = __shfl_sync(FULLM, hx, k);
        float x1 = __shfl_sync(FULLM, hy, k);
        acc += x0 * sW[(2 * k) * 8 + c] + x1 * sW[(2 * k + 1) * 8 + c];
    }
    if (sub == 0)
        g_H4[(size_t)node * 8 + c] = acc * d;
}

// ---------------- F4: aggregate 8d (fp32) + tanh + classifier -> d_out ----------
// d_out: [N*2 logits][N*8 hidden]
__global__ __launch_bounds__(256) void k_f4(
    const float* __restrict__ b4, const float* __restrict__ Wc,
    const float* __restrict__ bc, float* __restrict__ dout)
{
    int warp = (blockIdx.x * blockDim.x + threadIdx.x) >> 5;
    int lane = threadIdx.x & 31;
    if (warp >= N_NODES) return;
    const int node = warp;
    const float2* t = (const float2*)g_H4;
    int sub = lane >> 2;          // 8 subgroups
    int c   = lane & 3;

    float ax = 0.f, ay = 0.f, bx = 0.f, by = 0.f;
    if (sub == 0) {
        float2 s = t[(size_t)node * 4 + c];
        ax = s.x; ay = s.y;
    }
    int start = g_rowptr[node];
    int end   = g_rowptr[node + 1];
    int e = start + sub;
    for (; e + 24 < end; e += 32) {
        int s0 = g_srcs[e];
        int s1 = g_srcs[e + 8];
        int s2 = g_srcs[e + 16];
        int s3 = g_srcs[e + 24];
        float2 r0 = t[(size_t)s0 * 4 + c];
        float2 r1 = t[(size_t)s1 * 4 + c];
        float2 r2 = t[(size_t)s2 * 4 + c];
        float2 r3 = t[(size_t)s3 * 4 + c];
        ax += r0.x; ay += r0.y;
        bx += r1.x; by += r1.y;
        ax += r2.x; ay += r2.y;
        bx += r3.x; by += r3.y;
    }
    for (; e < end; e += 8) {
        float2 r = t[(size_t)g_srcs[e] * 4 + c];
        ax += r.x; ay += r.y;
    }
    ax += bx; ay += by;
    ax += __shfl_xor_sync(FULLM, ax, 4);
    ay += __shfl_xor_sync(FULLM, ay, 4);
    ax += __shfl_xor_sync(FULLM, ax, 8);
    ay += __shfl_xor_sync(FULLM, ay, 8);
    ax += __shfl_xor_sync(FULLM, ax, 16);
    ay += __shfl_xor_sync(FULLM, ay, 16);

    float d = g_dinv[node];
    float hx = tanhf(d * ax + b4[2 * c]);      // h4[2c]
    float hy = tanhf(d * ay + b4[2 * c + 1]);  // h4[2c+1]

    // classifier: logits over 8 features (pairs on lanes c=0..3)
    float p0 = hx * Wc[(2 * c) * 2 + 0] + hy * Wc[(2 * c + 1) * 2 + 0];
    float p1 = hx * Wc[(2 * c) * 2 + 1] + hy * Wc[(2 * c + 1) * 2 + 1];
    p0 += __shfl_xor_sync(FULLM, p0, 1);
    p1 += __shfl_xor_sync(FULLM, p1, 1);
    p0 += __shfl_xor_sync(FULLM, p0, 2);
    p1 += __shfl_xor_sync(FULLM, p1, 2);

    if (sub == 0) {
        float2* dh = (float2*)(dout + (size_t)2 * N_NODES);
        dh[(size_t)node * 4 + c] = make_float2(hx, hy);
        if (c == 0) {
            dout[(size_t)node * 2 + 0] = p0 + bc[0];
            dout[(size_t)node * 2 + 1] = p1 + bc[1];
        }
    }
}

// ---------------- launcher --------------------------------------------------------
extern "C" void kernel_launch(void* const* d_in, const int* in_sizes, int n_in,
                              void* d_out, int out_size)
{
    const float* x  = (const float*)d_in[0];
    const void*  ei = d_in[1];
    const float* W1 = (const float*)d_in[2];
    const float* b1 = (const float*)d_in[3];
    const float* W2 = (const float*)d_in[4];
    const float* b2 = (const float*)d_in[5];
    const float* W3 = (const float*)d_in[6];
    const float* b3 = (const float*)d_in[7];
    const float* W4 = (const float*)d_in[8];
    const float* b4 = (const float*)d_in[9];
    const float* Wc = (const float*)d_in[10];
    const float* bc = (const float*)d_in[11];
    float* out = (float*)d_out;

    const int nb = (N_NODES + TB - 1) / TB;
    const int wb = (N_NODES * 32 + TB - 1) / TB;  // one warp per node

    // CSR build (by dst) + dinv
    k_init<<<nb, TB>>>(ei);
    k_count<<<EB, TB>>>(ei);
    k_scan_local<<<SCAN_NBLK, SCAN_B>>>();
    k_scan_blk<<<1, 256>>>();
    k_scan_add<<<nb, TB>>>();

    // CSR fill + layer-1 GEMM co-scheduled in one launch
    k_fill_gemm1<<<EB + GB, TB>>>(ei, x, W1);

    // fused aggregate+GEMM pipeline
    k_f1<<<wb, TB>>>(b1, W2);
    k_f2<<<wb, TB>>>(b2, W3);
    k_f3<<<wb, TB>>>(b3, W4);
    k_f4<<<wb, TB>>>(b4, Wc, bc, out);
}